// round 16
// baseline (speedup 1.0000x reference)
#include <cuda_runtime.h>
#include <cuda_fp16.h>
#include <cstdint>

#define BATCH   4096
#define INDIM   1024
#define OUTDIM  1024
#define NNZ     52224

#define ROWS    64           // batch rows per CTA (2 per lane, fp16x2-packed)
#define THREADS 1024         // 32 warps
#define CPW     16           // columns per warp (512 cols per CTA / 32 warps)
#define WSTRIDE 33           // words per input column (32 row-pairs + 1 pad)
#define CAP     120          // max entries per column (mean ~51, max ~82)
#define CAP2    136          // list stride (16B-aligned)
#define SLD     516          // epilogue stage row stride (floats, 16B-aligned rows)
#define GRIDN   128          // all CTAs co-resident (1 per SM, 128 <= 148)
#define ENT     (NNZ / GRIDN)          // 408 entries scattered per CTA
#define COLPC   (OUTDIM / GRIDN)       // 8 columns padded per CTA

#define TILE_BYTES  (INDIM * WSTRIDE * 4)          // 135168
#define STAGE_OFF   TILE_BYTES                     // per-warp entry staging after tile
#define WARP_STAGE  2048                           // 2 bufs x (512 ii + 512 w)
#define SMEM_TOTAL  (TILE_BYTES + 32 * WARP_STAGE) // 200704

// Device scratch (allocation-free rule). All zero at module load; g_len and
// the barrier counters are reset in-kernel every launch (deterministic).
__device__ int g_len[OUTDIM];
__device__ __align__(16) unsigned char g_lq8[OUTDIM];  // 8-entry blocks per column
__device__ __align__(16) unsigned g_ii[OUTDIM * CAP2]; // BYTE offsets: ind_in*WSTRIDE*4
__device__ __align__(16) unsigned g_wh[OUTDIM * CAP2]; // weight as DUPLICATED half2 (w,w)
__device__ int g_barA, g_barB, g_barC;                 // grid-barrier counters

__device__ __forceinline__ unsigned h2_as_u32(__half2 h) {
    union { __half2 h; unsigned u; } cvt; cvt.h = h; return cvt.u;
}
__device__ __forceinline__ __half2 u32_as_h2(unsigned u) {
    union { unsigned u; __half2 h; } cvt; cvt.u = u; return cvt.h;
}
__device__ __forceinline__ uint32_t smem_u32(const void* p) {
    uint32_t a;
    asm("{ .reg .u64 t; cvta.to.shared.u64 t, %1; cvt.u32.u64 %0, t; }" : "=r"(a) : "l"(p));
    return a;
}

// Software grid barrier: safe because all GRIDN CTAs are co-resident.
__device__ __forceinline__ void grid_bar(int* ctr) {
    __syncthreads();
    if (threadIdx.x == 0) {
        __threadfence();                       // make this CTA's writes visible
        atomicAdd(ctr, 1);
        while (atomicAdd(ctr, 0) < GRIDN) { }  // L2 poll
        __threadfence();
    }
    __syncthreads();
}

// ---------------- fused kernel ----------------
//
// Phase 1: each CTA scatters its 408 entries into per-column lists (atomics),
//          overlapped with Phase 2 (tile fill: fp16x2 row-pair packing).
// Barrier A. Phase 3: each CTA pads its 8 columns to a multiple of 8 entries,
// records length bytes, resets g_len. Barrier B. Then the gather engine:
// cp.async double-buffered lists, one HFMA2 per entry (64 rows/LDS.32),
// fp32 flush per 8-entry block, swizzled epilogue stage, coalesced stores.

__global__ __launch_bounds__(THREADS, 1)
void k_fused(const float* __restrict__ input,
             const float* __restrict__ bias,
             float* __restrict__ out,
             const int* __restrict__ ind_in,
             const int* __restrict__ ind_out,
             const float* __restrict__ weight) {
    extern __shared__ __align__(16) char smem[];
    unsigned* sw = (unsigned*)smem;
    const uint32_t sb  = smem_u32(smem);
    const int tid      = threadIdx.x;
    const int tile     = blockIdx.x >> 1;
    const int ch       = blockIdx.x & 1;          // column half: 0 or 1
    const int base_row = tile * ROWS;
    const int jbase    = ch * (OUTDIM / 2);
    const int warp = tid >> 5;
    const int lane = tid & 31;
    const int jwarp = jbase + warp * CPW;

    // ---- Phase 1: entry scatter (this CTA's slice of NNZ) ----
    if (tid < ENT) {
        int k = blockIdx.x * ENT + tid;
        int j = ind_out[k];
        int p = atomicAdd(&g_len[j], 1);
        if (p < CAP) {
            float w = weight[k];
            g_ii[j * CAP2 + p] = (unsigned)(ind_in[k] * (WSTRIDE * 4));
            g_wh[j * CAP2 + p] = h2_as_u32(__floats2half2_rn(w, w));
        }
    }

    // ---- Phase 2: tile fill (independent of phase 1) ----
    #pragma unroll
    for (int it = 0; it < 8; ++it) {
        int idx = it * THREADS + tid;             // 8192 = 32 row-pairs x 256 col-quads
        int rp  = idx >> 8;
        int c4  = idx & 255;
        const float4 a = *(const float4*)(input + (size_t)(base_row + 2 * rp)     * INDIM + c4 * 4);
        const float4 b = *(const float4*)(input + (size_t)(base_row + 2 * rp + 1) * INDIM + c4 * 4);
        sw[(4 * c4 + 0) * WSTRIDE + rp] = h2_as_u32(__floats2half2_rn(a.x, b.x));
        sw[(4 * c4 + 1) * WSTRIDE + rp] = h2_as_u32(__floats2half2_rn(a.y, b.y));
        sw[(4 * c4 + 2) * WSTRIDE + rp] = h2_as_u32(__floats2half2_rn(a.z, b.z));
        sw[(4 * c4 + 3) * WSTRIDE + rp] = h2_as_u32(__floats2half2_rn(a.w, b.w));
    }

    grid_bar(&g_barA);                            // all scatters + fills visible

    // ---- Phase 3: pad this CTA's 8 columns; reset lengths ----
    if (tid < COLPC) {
        int j  = blockIdx.x * COLPC + tid;
        int n  = min(g_len[j], CAP);
        int n8 = (n + 7) & ~7;
        for (int p = n; p < n8; ++p) {
            g_ii[j * CAP2 + p] = 0u;
            g_wh[j * CAP2 + p] = 0u;
        }
        g_lq8[j] = (unsigned char)(n8 >> 3);
        g_len[j] = 0;                             // self-reset for next replay
    }

    grid_bar(&g_barB);                            // all pads visible

    // ---- gather engine (R15) ----
    auto prefetch_col = [&](int c, int buf) {
        const int j = jwarp + c;
        const char* gii = (const char*)(g_ii + j * CAP2) + lane * 16;
        const char* gw  = (const char*)(g_wh + j * CAP2) + lane * 16;
        uint32_t dII = sb + STAGE_OFF + warp * WARP_STAGE + buf * 1024 + lane * 16;
        asm volatile("cp.async.cg.shared.global [%0], [%1], 16;" :: "r"(dII), "l"(gii));
        asm volatile("cp.async.cg.shared.global [%0], [%1], 16;" :: "r"(dII + 512u), "l"(gw));
        asm volatile("cp.async.commit_group;" ::: "memory");
    };

    prefetch_col(0, 0);
    prefetch_col(1, 1);

    const uint4 lqv = *(const uint4*)(g_lq8 + jwarp);   // 16 lengths, one LDG.128
    const unsigned lqw[4] = {lqv.x, lqv.y, lqv.z, lqv.w};

    const char* lane_base = (const char*)smem + lane * 4;
    float accE[CPW], accO[CPW];                   // rows 2*lane / 2*lane+1

    #pragma unroll
    for (int c = 0; c < CPW; ++c) {
        if (c < CPW - 1) asm volatile("cp.async.wait_group 1;" ::: "memory");
        else             asm volatile("cp.async.wait_group 0;" ::: "memory");
        __syncwarp();

        const int L8 = (int)((lqw[c >> 2] >> ((c & 3) * 8)) & 0xFF);
        const char* stg = smem + STAGE_OFF + warp * WARP_STAGE + (c & 1) * 1024;
        const uint4* ip = (const uint4*)(stg);
        const uint4* wp = (const uint4*)(stg + 512);

        float a0 = 0.f, a1 = 0.f, b0 = 0.f, b1 = 0.f;
        #pragma unroll 1
        for (int p = 0; p < L8; ++p) {
            uint4 i0 = ip[2 * p];
            uint4 w0 = wp[2 * p];
            uint4 i1 = ip[2 * p + 1];
            uint4 w1 = wp[2 * p + 1];
            __half2 A = __floats2half2_rn(0.f, 0.f);
            __half2 B = __floats2half2_rn(0.f, 0.f);
            A = __hfma2(*(const __half2*)(lane_base + i0.x), u32_as_h2(w0.x), A);
            B = __hfma2(*(const __half2*)(lane_base + i0.y), u32_as_h2(w0.y), B);
            A = __hfma2(*(const __half2*)(lane_base + i0.z), u32_as_h2(w0.z), A);
            B = __hfma2(*(const __half2*)(lane_base + i0.w), u32_as_h2(w0.w), B);
            A = __hfma2(*(const __half2*)(lane_base + i1.x), u32_as_h2(w1.x), A);
            B = __hfma2(*(const __half2*)(lane_base + i1.y), u32_as_h2(w1.y), B);
            A = __hfma2(*(const __half2*)(lane_base + i1.z), u32_as_h2(w1.z), A);
            B = __hfma2(*(const __half2*)(lane_base + i1.w), u32_as_h2(w1.w), B);
            float2 fA = __half22float2(A);
            float2 fB = __half22float2(B);
            a0 += fA.x;  a1 += fA.y;
            b0 += fB.x;  b1 += fB.y;
        }
        accE[c] = a0 + b0;
        accO[c] = a1 + b1;

        if (c + 2 < CPW) prefetch_col(c + 2, c & 1);
    }

    // ---- epilogue: swizzled stage, then coalesced float4 stores ----
    __syncthreads();                              // all gathers done; reuse tile smem
    float* st = (float*)smem;
    {
        const int key = lane & 7;
        #pragma unroll
        for (int c = 0; c < CPW; ++c) {
            int lcol = warp * CPW + c;
            int g    = lcol >> 2;
            int w    = lcol & 3;
            int off  = 4 * (g ^ key) + w;
            st[(2 * lane)     * SLD + off] = accE[c];
            st[(2 * lane + 1) * SLD + off] = accO[c];
        }
    }
    __syncthreads();

    #pragma unroll
    for (int it = 0; it < 8; ++it) {
        int idx = it * THREADS + tid;             // 8192 float4 = 64 rows x 128 groups
        int row = idx >> 7;
        int c4  = idx & 127;
        int key = (row >> 1) & 7;
        float4 v  = *(const float4*)(st + row * SLD + 4 * (c4 ^ key));
        float4 bz = *(const float4*)(bias + jbase + c4 * 4);
        v.x += bz.x; v.y += bz.y; v.z += bz.z; v.w += bz.w;
        *(float4*)(out + (size_t)(base_row + row) * OUTDIM + jbase + c4 * 4) = v;
    }

    // ---- last-one-out resets the barrier counters for the next replay ----
    __syncthreads();
    if (tid == 0) {
        int c = atomicAdd(&g_barC, 1);
        if (c == GRIDN - 1) { g_barA = 0; g_barB = 0; g_barC = 0; }
    }
}

// ---------------- launch ----------------

extern "C" void kernel_launch(void* const* d_in, const int* in_sizes, int n_in,
                              void* d_out, int out_size) {
    const float* input   = (const float*)d_in[0];   // [4096,1024] f32
    const float* weight  = (const float*)d_in[1];   // [52224]     f32
    const float* bias    = (const float*)d_in[2];   // [1024]      f32
    const int*   ind_in  = (const int*)  d_in[3];   // [52224]     i32
    const int*   ind_out = (const int*)  d_in[4];   // [52224]     i32
    float*       out     = (float*)d_out;           // [4096,1024] f32

    cudaFuncSetAttribute(k_fused, cudaFuncAttributeMaxDynamicSharedMemorySize, SMEM_TOTAL);

    k_fused<<<GRIDN, THREADS, SMEM_TOTAL>>>(input, bias, out, ind_in, ind_out, weight);
}

// round 17
// speedup vs baseline: 1.0464x; 1.0464x over previous
#include <cuda_runtime.h>
#include <cuda_fp16.h>
#include <cstdint>

#define BATCH   4096
#define INDIM   1024
#define OUTDIM  1024
#define NNZ     52224

#define ROWS    64           // batch rows per CTA (2 per lane, fp16x2-packed)
#define THREADS 1024         // 32 warps
#define CPW     16           // columns per warp (512 cols per CTA / 32 warps)
#define WSTRIDE 33           // words per input column (32 row-pairs + 1 pad)
#define CAP     120          // max entries per column (mean ~51, max ~82)
#define CAP2    136          // list stride (16B-aligned)
#define SLD     516          // epilogue stage row stride (floats, 16B-aligned rows)

#define TILE_BYTES  (INDIM * WSTRIDE * 4)          // 135168
#define STAGE_OFF   TILE_BYTES                     // per-warp entry staging after tile
#define WARP_STAGE  2048                           // 2 bufs x (512 ii + 512 w)
#define SMEM_TOTAL  (TILE_BYTES + 32 * WARP_STAGE) // 200704

// Device scratch (allocation-free rule). Counters SPREAD one per 128B line
// to parallelize L2 atomic serialization across LTS slices; self-reset in
// k_pad each launch (zero at module load) -> no k_zero kernel.
__device__ int g_len[OUTDIM * 32];                     // counter at j*32
__device__ __align__(16) unsigned char g_lq8[OUTDIM];  // 8-entry blocks per column
__device__ __align__(16) unsigned g_ii[OUTDIM * CAP2]; // BYTE offsets: ind_in*WSTRIDE*4
__device__ __align__(16) unsigned g_wh[OUTDIM * CAP2]; // weight as DUPLICATED half2 (w,w)

__device__ __forceinline__ unsigned h2_as_u32(__half2 h) {
    union { __half2 h; unsigned u; } cvt; cvt.h = h; return cvt.u;
}
__device__ __forceinline__ __half2 u32_as_h2(unsigned u) {
    union { unsigned u; __half2 h; } cvt; cvt.u = u; return cvt.h;
}
__device__ __forceinline__ uint32_t smem_u32(const void* p) {
    uint32_t a;
    asm("{ .reg .u64 t; cvta.to.shared.u64 t, %1; cvt.u32.u64 %0, t; }" : "=r"(a) : "l"(p));
    return a;
}

// ---------------- preprocessing: bucket NNZ by output column ----------------

__global__ void k_fill(const int* __restrict__ ind_in,
                       const int* __restrict__ ind_out,
                       const float* __restrict__ weight) {
    int k = blockIdx.x * blockDim.x + threadIdx.x;
    if (k < NNZ) {
        int j = ind_out[k];
        int p = atomicAdd(&g_len[j << 5], 1);          // spread counter: own 128B line
        if (p < CAP) {
            float w = weight[k];
            g_ii[j * CAP2 + p] = (unsigned)(ind_in[k] * (WSTRIDE * 4));
            g_wh[j * CAP2 + p] = h2_as_u32(__floats2half2_rn(w, w));
        }
    }
}

// Pad each list to a multiple of 8 entries; record 8-blocks; reset counter.
__global__ void k_pad() {
    int j = blockIdx.x * blockDim.x + threadIdx.x;
    if (j < OUTDIM) {
        int n  = min(g_len[j << 5], CAP);
        int n8 = (n + 7) & ~7;
        for (int p = n; p < n8; ++p) {
            g_ii[j * CAP2 + p] = 0u;
            g_wh[j * CAP2 + p] = 0u;
        }
        g_lq8[j] = (unsigned char)(n8 >> 3);
        g_len[j << 5] = 0;                             // self-reset for next replay
    }
}

// ---------------- main kernel ----------------
//
// CTA = 64 batch rows x 512 output cols. Input tile in smem as fp16x2:
// word[col*33 + rp] packs rows (2rp, 2rp+1); one conflict-free LDS.32 per
// entry gathers 64 rows. Entry lists (ii + half2-dup weights) double-buffered
// into smem via cp.async. Hot loop: ONE HFMA2 per entry, FOUR independent
// half2 chains (depth 2), fp32 flush per 8-entry block. Swizzled epilogue.

__global__ __launch_bounds__(THREADS, 1)
void k_main(const float* __restrict__ input,
            const float* __restrict__ bias,
            float* __restrict__ out) {
    extern __shared__ __align__(16) char smem[];
    unsigned* sw = (unsigned*)smem;
    const uint32_t sb  = smem_u32(smem);
    const int tid      = threadIdx.x;
    const int tile     = blockIdx.x >> 1;
    const int ch       = blockIdx.x & 1;          // column half: 0 or 1
    const int base_row = tile * ROWS;
    const int jbase    = ch * (OUTDIM / 2);

    const int warp = tid >> 5;
    const int lane = tid & 31;
    const int jwarp = jbase + warp * CPW;

    // cp.async staging: lane l copies ii-quad l and w-quad l of the column
    auto prefetch_col = [&](int c, int buf) {
        const int j = jwarp + c;
        const char* gii = (const char*)(g_ii + j * CAP2) + lane * 16;
        const char* gw  = (const char*)(g_wh + j * CAP2) + lane * 16;
        uint32_t dII = sb + STAGE_OFF + warp * WARP_STAGE + buf * 1024 + lane * 16;
        asm volatile("cp.async.cg.shared.global [%0], [%1], 16;" :: "r"(dII), "l"(gii));
        asm volatile("cp.async.cg.shared.global [%0], [%1], 16;" :: "r"(dII + 512u), "l"(gw));
        asm volatile("cp.async.commit_group;" ::: "memory");
    };

    // Kick off the first two columns' lists before touching the tile
    prefetch_col(0, 0);
    prefetch_col(1, 1);

    // All 16 column lengths in one broadcast LDG.128 (u8 each)
    const uint4 lqv = *(const uint4*)(g_lq8 + jwarp);
    const unsigned lqw[4] = {lqv.x, lqv.y, lqv.z, lqv.w};

    // ---- fill: pack rows (2rp, 2rp+1) as fp16x2, word[col*33 + rp] ----
    #pragma unroll
    for (int it = 0; it < 8; ++it) {
        int idx = it * THREADS + tid;             // 8192 = 32 row-pairs x 256 col-quads
        int rp  = idx >> 8;
        int c4  = idx & 255;
        const float4 a = *(const float4*)(input + (size_t)(base_row + 2 * rp)     * INDIM + c4 * 4);
        const float4 b = *(const float4*)(input + (size_t)(base_row + 2 * rp + 1) * INDIM + c4 * 4);
        sw[(4 * c4 + 0) * WSTRIDE + rp] = h2_as_u32(__floats2half2_rn(a.x, b.x));
        sw[(4 * c4 + 1) * WSTRIDE + rp] = h2_as_u32(__floats2half2_rn(a.y, b.y));
        sw[(4 * c4 + 2) * WSTRIDE + rp] = h2_as_u32(__floats2half2_rn(a.z, b.z));
        sw[(4 * c4 + 3) * WSTRIDE + rp] = h2_as_u32(__floats2half2_rn(a.w, b.w));
    }
    __syncthreads();

    const char* lane_base = (const char*)smem + lane * 4;
    float accE[CPW], accO[CPW];                   // rows 2*lane / 2*lane+1

    #pragma unroll
    for (int c = 0; c < CPW; ++c) {
        // Wait for THIS column's group (last column: drain everything)
        if (c < CPW - 1) asm volatile("cp.async.wait_group 1;" ::: "memory");
        else             asm volatile("cp.async.wait_group 0;" ::: "memory");
        __syncwarp();

        const int L8 = (int)((lqw[c >> 2] >> ((c & 3) * 8)) & 0xFF);
        const char* stg = smem + STAGE_OFF + warp * WARP_STAGE + (c & 1) * 1024;
        const uint4* ip = (const uint4*)(stg);
        const uint4* wp = (const uint4*)(stg + 512);

        float a0 = 0.f, a1 = 0.f, b0 = 0.f, b1 = 0.f;
        #pragma unroll 1
        for (int p = 0; p < L8; ++p) {
            uint4 i0 = ip[2 * p];
            uint4 w0 = wp[2 * p];
            uint4 i1 = ip[2 * p + 1];
            uint4 w1 = wp[2 * p + 1];
            const __half2 Z = __floats2half2_rn(0.f, 0.f);
            __half2 A = Z, B = Z, C = Z, D = Z;   // 4 independent chains, depth 2
            A = __hfma2(*(const __half2*)(lane_base + i0.x), u32_as_h2(w0.x), A);
            B = __hfma2(*(const __half2*)(lane_base + i0.y), u32_as_h2(w0.y), B);
            C = __hfma2(*(const __half2*)(lane_base + i0.z), u32_as_h2(w0.z), C);
            D = __hfma2(*(const __half2*)(lane_base + i0.w), u32_as_h2(w0.w), D);
            A = __hfma2(*(const __half2*)(lane_base + i1.x), u32_as_h2(w1.x), A);
            B = __hfma2(*(const __half2*)(lane_base + i1.y), u32_as_h2(w1.y), B);
            C = __hfma2(*(const __half2*)(lane_base + i1.z), u32_as_h2(w1.z), C);
            D = __hfma2(*(const __half2*)(lane_base + i1.w), u32_as_h2(w1.w), D);
            __half2 P = __hadd2(A, C);
            __half2 Q = __hadd2(B, D);
            float2 fP = __half22float2(P);
            float2 fQ = __half22float2(Q);
            a0 += fP.x;  a1 += fP.y;
            b0 += fQ.x;  b1 += fQ.y;
        }
        accE[c] = a0 + b0;
        accO[c] = a1 + b1;

        // Refill the buffer we just finished with column c+2
        if (c + 2 < CPW) prefetch_col(c + 2, c & 1);
    }

    // ---- epilogue: swizzled stage, then coalesced float4 stores ----
    __syncthreads();                              // all gathers done; reuse tile smem
    float* st = (float*)smem;
    {
        const int key = lane & 7;
        #pragma unroll
        for (int c = 0; c < CPW; ++c) {
            int lcol = warp * CPW + c;            // compile-time c -> no spills
            int g    = lcol >> 2;
            int w    = lcol & 3;
            int off  = 4 * (g ^ key) + w;
            st[(2 * lane)     * SLD + off] = accE[c];
            st[(2 * lane + 1) * SLD + off] = accO[c];
        }
    }
    __syncthreads();

    #pragma unroll
    for (int it = 0; it < 8; ++it) {
        int idx = it * THREADS + tid;             // 8192 float4 = 64 rows x 128 groups
        int row = idx >> 7;
        int c4  = idx & 127;
        int key = (row >> 1) & 7;
        float4 v  = *(const float4*)(st + row * SLD + 4 * (c4 ^ key));
        float4 bz = *(const float4*)(bias + jbase + c4 * 4);
        v.x += bz.x; v.y += bz.y; v.z += bz.z; v.w += bz.w;
        *(float4*)(out + (size_t)(base_row + row) * OUTDIM + jbase + c4 * 4) = v;
    }
}

// ---------------- launch ----------------

extern "C" void kernel_launch(void* const* d_in, const int* in_sizes, int n_in,
                              void* d_out, int out_size) {
    const float* input   = (const float*)d_in[0];   // [4096,1024] f32
    const float* weight  = (const float*)d_in[1];   // [52224]     f32
    const float* bias    = (const float*)d_in[2];   // [1024]      f32
    const int*   ind_in  = (const int*)  d_in[3];   // [52224]     i32
    const int*   ind_out = (const int*)  d_in[4];   // [52224]     i32
    float*       out     = (float*)d_out;           // [4096,1024] f32

    cudaFuncSetAttribute(k_main, cudaFuncAttributeMaxDynamicSharedMemorySize, SMEM_TOTAL);

    k_fill<<<(NNZ + 255) / 256, 256>>>(ind_in, ind_out, weight);
    k_pad <<<(OUTDIM + 255) / 256, 256>>>();
    k_main<<<(BATCH / ROWS) * 2, THREADS, SMEM_TOTAL>>>(input, bias, out);
}